// round 12
// baseline (speedup 1.0000x reference)
#include <cuda_runtime.h>
#include <math.h>

// Cox partial likelihood, 2 kernels (v12):
//   K1 (64 CTAs x 256): count-rank sort per chunk of 256 (packed keys in SMEM,
//     rank_i = #{kv_m < kv_i} via broadcast LDS.128), scatter, suffix-scan e.
//   K2 (256 CTAs x 512): CTA (tile, grp) stages 8 chunks' keys+sfx (~16KB);
//     each thread: 8 independent depth-8 SMEM searches for its slot key,
//     partial rss -> plain store. Ticket (1 atomic/CTA): LAST CTA sums the
//     8 partials per slot, computes loss terms, reduces, writes out.

#define NN     16384
#define CH     256
#define NCH    64                // NN / CH
#define RB     512               // K2 block size
#define TILES  (NN / RB)         // 32
#define GROUPS 8
#define CPG    (NCH / GROUPS)    // 8 chunks per group
#define K2G    (TILES * GROUPS)  // 256 CTAs

typedef unsigned long long ull;

__device__ unsigned g_u  [NN];               // sorted keys, chunk-major
__device__ float    g_sfx[NCH * (CH + 1)];   // suffix sums (+0 sentinel)
__device__ int      g_idx[NN];               // original index per sorted slot
__device__ float    g_part[GROUPS * NN];     // per-group partial rss
__device__ unsigned g_tk;                    // completion ticket (0-init, self-reset)

__device__ __forceinline__ unsigned key_of(float t) {
    unsigned b = __float_as_uint(t);
    return b ^ ((unsigned)((int)b >> 31) | 0x80000000u);   // never 0 for finite t
}

__global__ void __launch_bounds__(CH)
sort_kernel(const float* __restrict__ theta, const float* __restrict__ T, int n) {
    __shared__ ull   skv[CH];
    __shared__ float se [CH];
    __shared__ float swarp[CH / 32];
    __shared__ float soff [CH / 32];

    const int c    = blockIdx.x;
    const int t    = threadIdx.x;
    const int lane = t & 31;
    const int w    = t >> 5;
    const int j    = c * CH + t;

    const float e  = (j < n) ? expf(theta[j]) : 0.0f;
    const ull   kv = (j < n) ? (((ull)key_of(T[j]) << 32) | (unsigned)j) : (ull)t;
    skv[t] = kv;
    __syncthreads();

    int rank = 0;
    const ulonglong2* p2 = (const ulonglong2*)skv;
#pragma unroll 8
    for (int m = 0; m < CH / 2; m++) {
        ulonglong2 v = p2[m];                 // broadcast LDS.128
        rank += (v.x < kv) + (v.y < kv);
    }

    g_u  [c * CH + rank] = (unsigned)(kv >> 32);
    g_idx[c * CH + rank] = (int)(unsigned)kv;
    se[rank] = e;
    __syncthreads();

    float ssum = se[t];
#pragma unroll
    for (int off = 1; off < 32; off <<= 1) {
        float v = __shfl_down_sync(0xFFFFFFFFu, ssum, off);
        if (lane + off < 32) ssum += v;
    }
    if (lane == 0) swarp[w] = ssum;
    __syncthreads();
    if (t < CH / 32) {
        float v = swarp[t];
#pragma unroll
        for (int off = 1; off < CH / 32; off <<= 1) {
            float x = __shfl_down_sync(0xFFu, v, off);
            if (t + off < CH / 32) v += x;
        }
        soff[t] = v - swarp[t];
    }
    __syncthreads();

    g_sfx[c * (CH + 1) + t] = ssum + soff[w];
    if (t == 0) g_sfx[c * (CH + 1) + CH] = 0.0f;
}

extern "C" __global__ void __launch_bounds__(RB)
rank_loss_kernel(const float* __restrict__ theta, const float* __restrict__ ev,
                 int n, float* __restrict__ out) {
    __shared__ unsigned ck[CPG][CH];
    __shared__ float    cs[CPG][CH + 1];
    __shared__ float    wsum[RB / 32];
    __shared__ unsigned slast;

    const int b    = blockIdx.x;
    const int tile = b >> 3;                  // b / GROUPS
    const int grp  = b & (GROUPS - 1);
    const int t    = threadIdx.x;

    const unsigned u = g_u[tile * RB + t];    // my slot key

    for (int i = t; i < CPG * CH; i += RB) {
        const int q = i >> 8, r = i & (CH - 1);
        ck[q][r] = g_u[(grp * CPG + q) * CH + r];
    }
    for (int i = t; i < CPG * (CH + 1); i += RB) {
        const int q = i / (CH + 1), r = i % (CH + 1);
        cs[q][r] = g_sfx[(grp * CPG + q) * (CH + 1) + r];
    }
    __syncthreads();

    int lo[CPG];
#pragma unroll
    for (int q = 0; q < CPG; q++) lo[q] = 0;
#pragma unroll
    for (int s = CH / 2; s > 0; s >>= 1) {    // 8 levels, ILP=8
#pragma unroll
        for (int q = 0; q < CPG; q++)
            if (ck[q][lo[q] + s - 1] < u) lo[q] += s;
    }

    float acc = 0.0f;
#pragma unroll
    for (int q = 0; q < CPG; q++) acc += cs[q][lo[q]];
    g_part[grp * NN + tile * RB + t] = acc;

    // ---- ticket: exactly one fence+atomic per CTA; non-winners exit ----
    __syncthreads();
    if (t == 0) {
        __threadfence();
        slast = atomicAdd(&g_tk, 1u);
    }
    __syncthreads();
    if (slast != K2G - 1) return;

    // ---- last CTA: loss over all slots ----
    if (t == 0) __threadfence();              // acquire all partials
    __syncthreads();

    float term = 0.0f;
#pragma unroll 1
    for (int r = 0; r < NN / RB; r++) {       // 32 slots per thread
        const int s = r * RB + t;
        float rss = 0.0f;
#pragma unroll
        for (int g = 0; g < GROUPS; g++) rss += g_part[g * NN + s];
        const int io = g_idx[s];
        term += (theta[io] - logf(rss)) * ev[io];
    }

    for (int off = 16; off > 0; off >>= 1)
        term += __shfl_down_sync(0xFFFFFFFFu, term, off);
    const int lane = t & 31, w = t >> 5;
    if (lane == 0) wsum[w] = term;
    __syncthreads();
    if (t == 0) {
        float s = 0.0f;
#pragma unroll
        for (int ww = 0; ww < RB / 32; ww++) s += wsum[ww];
        out[0] = -s / (float)n;
        g_tk = 0;                             // reset for next graph replay
    }
}

extern "C" void kernel_launch(void* const* d_in, const int* in_sizes, int n_in,
                              void* d_out, int out_size) {
    const float* theta = (const float*)d_in[0];
    const float* T     = (const float*)d_in[1];
    const float* ev    = (const float*)d_in[2];
    float*       out   = (float*)d_out;
    const int n = in_sizes[0];

    sort_kernel<<<NCH, CH>>>(theta, T, n);
    rank_loss_kernel<<<K2G, RB>>>(theta, ev, n, out);
}

// round 14
// speedup vs baseline: 1.9670x; 1.9670x over previous
#include <cuda_runtime.h>
#include <math.h>

// Cox partial likelihood, 3 kernels (v13 = measured-best pieces):
//   K1 (64 CTAs x 256): count-rank sort per chunk of 256 — packed
//     (key(T)<<32|idx) staged in SMEM, rank_i = #{kv_m < kv_i} via broadcast
//     LDS.128; scatter key/idx/e; shuffle suffix-scan of e. Zeros out.
//     [measured 1.3us in R11]
//   K2 (512 CTAs x 512): CTA (tile, grp) stages 4 chunks' keys+sfx (~8KB);
//     each thread: 4 independent depth-8 SMEM searches; partial rss -> store.
//   K3 (32 CTAs x 512): sum 16 partials/slot, gather theta/ev via idx,
//     block-reduce, one atomicAdd(out) per CTA.

#define NN     16384
#define CH     256
#define NCH    64                // NN / CH
#define RB     512               // K2/K3 block size
#define TILES  (NN / RB)         // 32
#define GROUPS 16
#define CPG    (NCH / GROUPS)    // 4 chunks per group

typedef unsigned long long ull;

__device__ unsigned g_u  [NN];               // sorted keys, chunk-major
__device__ float    g_sfx[NCH * (CH + 1)];   // suffix sums (+0 sentinel)
__device__ int      g_idx[NN];               // original index per sorted slot
__device__ float    g_part[GROUPS * NN];     // per-group partial rss

__device__ __forceinline__ unsigned key_of(float t) {
    unsigned b = __float_as_uint(t);
    return b ^ ((unsigned)((int)b >> 31) | 0x80000000u);   // never 0 for finite t
}

__global__ void __launch_bounds__(CH)
sort_kernel(const float* __restrict__ theta, const float* __restrict__ T,
            int n, float* __restrict__ out) {
    __shared__ ull   skv[CH];
    __shared__ float se [CH];
    __shared__ float swarp[CH / 32];
    __shared__ float soff [CH / 32];

    const int c    = blockIdx.x;
    const int t    = threadIdx.x;
    const int lane = t & 31;
    const int w    = t >> 5;
    const int j    = c * CH + t;

    const float e  = (j < n) ? expf(theta[j]) : 0.0f;
    const ull   kv = (j < n) ? (((ull)key_of(T[j]) << 32) | (unsigned)j) : (ull)t;
    skv[t] = kv;
    __syncthreads();

    // rank = #{ m : skv[m] < kv }  (keys unique via idx low bits)
    int rank = 0;
    const ulonglong2* p2 = (const ulonglong2*)skv;
#pragma unroll 8
    for (int m = 0; m < CH / 2; m++) {
        ulonglong2 v = p2[m];                 // broadcast LDS.128
        rank += (v.x < kv) + (v.y < kv);
    }

    g_u  [c * CH + rank] = (unsigned)(kv >> 32);
    g_idx[c * CH + rank] = (int)(unsigned)kv;
    se[rank] = e;
    __syncthreads();

    // inclusive suffix sum of se over sorted positions
    float ssum = se[t];
#pragma unroll
    for (int off = 1; off < 32; off <<= 1) {
        float v = __shfl_down_sync(0xFFFFFFFFu, ssum, off);
        if (lane + off < 32) ssum += v;
    }
    if (lane == 0) swarp[w] = ssum;
    __syncthreads();
    if (t < CH / 32) {
        float v = swarp[t];
#pragma unroll
        for (int off = 1; off < CH / 32; off <<= 1) {
            float x = __shfl_down_sync(0xFFu, v, off);
            if (t + off < CH / 32) v += x;
        }
        soff[t] = v - swarp[t];
    }
    __syncthreads();

    g_sfx[c * (CH + 1) + t] = ssum + soff[w];
    if (t == 0) {
        g_sfx[c * (CH + 1) + CH] = 0.0f;
        if (c == 0) out[0] = 0.0f;            // stream-ordered before K3
    }
}

__global__ void __launch_bounds__(RB)
rank_kernel() {
    __shared__ unsigned ck[CPG][CH];
    __shared__ float    cs[CPG][CH + 1];

    const int b    = blockIdx.x;
    const int tile = b / GROUPS;
    const int grp  = b % GROUPS;
    const int t    = threadIdx.x;

    const unsigned u = g_u[tile * RB + t];    // my slot key

    for (int i = t; i < CPG * CH; i += RB) {
        const int q = i >> 8, r = i & (CH - 1);
        ck[q][r] = g_u[(grp * CPG + q) * CH + r];
    }
    for (int i = t; i < CPG * (CH + 1); i += RB) {
        const int q = i / (CH + 1), r = i % (CH + 1);
        cs[q][r] = g_sfx[(grp * CPG + q) * (CH + 1) + r];
    }
    __syncthreads();

    int lo[CPG];
#pragma unroll
    for (int q = 0; q < CPG; q++) lo[q] = 0;
#pragma unroll
    for (int s = CH / 2; s > 0; s >>= 1) {    // 8 levels, ILP=4
#pragma unroll
        for (int q = 0; q < CPG; q++)
            if (ck[q][lo[q] + s - 1] < u) lo[q] += s;
    }

    float acc = 0.0f;
#pragma unroll
    for (int q = 0; q < CPG; q++) acc += cs[q][lo[q]];

    g_part[grp * NN + tile * RB + t] = acc;
}

__global__ void __launch_bounds__(RB)
loss_kernel(const float* __restrict__ theta, const float* __restrict__ ev,
            int n, float* __restrict__ out) {
    const int s = blockIdx.x * RB + threadIdx.x;

    float term = 0.0f;
    if (s < n) {
        float rss = 0.0f;
#pragma unroll
        for (int g = 0; g < GROUPS; g++) rss += g_part[g * NN + s];
        const int io = g_idx[s];
        term = (theta[io] - logf(rss)) * ev[io];
    }

    for (int off = 16; off > 0; off >>= 1)
        term += __shfl_down_sync(0xFFFFFFFFu, term, off);

    __shared__ float wsum[RB / 32];
    const int lane = threadIdx.x & 31, warp = threadIdx.x >> 5;
    if (lane == 0) wsum[warp] = term;
    __syncthreads();
    if (threadIdx.x == 0) {
        float ssum = 0.0f;
#pragma unroll
        for (int w = 0; w < RB / 32; w++) ssum += wsum[w];
        atomicAdd(out, -ssum / (float)n);
    }
}

extern "C" void kernel_launch(void* const* d_in, const int* in_sizes, int n_in,
                              void* d_out, int out_size) {
    const float* theta = (const float*)d_in[0];
    const float* T     = (const float*)d_in[1];
    const float* ev    = (const float*)d_in[2];
    float*       out   = (float*)d_out;
    const int n = in_sizes[0];

    sort_kernel<<<NCH, CH>>>(theta, T, n, out);
    rank_kernel<<<TILES * GROUPS, RB>>>();
    loss_kernel<<<TILES, RB>>>(theta, ev, n, out);
}

// round 16
// speedup vs baseline: 2.2381x; 1.1378x over previous
#include <cuda_runtime.h>
#include <math.h>

// Cox partial likelihood, 3 kernels (v15 = v14 with lower_bound off-by-one fixed):
//   K1 (64 CTAs x 256): chunk = 8 warp-runs of 32; warp-bitonic register sort of
//     packed (key<<32|idx); rank = lane + full lower_bound (range [0,32]) in the
//     7 other runs (ILP=7); scatter; shuffle suffix-scan of e.
//   K2 (512 CTAs x 512): 4 chunks staged in SMEM; full lower_bound [0,256] per
//     chunk (ILP=4); partial rss -> plain store.
//   K3 (32 CTAs x 512): sum 16 partials, gather theta/ev, reduce, atomicAdd.

#define NN     16384
#define CH     256
#define NCH    64
#define RB     512
#define TILES  (NN / RB)         // 32
#define GROUPS 16
#define CPG    (NCH / GROUPS)    // 4

typedef unsigned long long ull;

__device__ unsigned g_u  [NN];
__device__ float    g_sfx[NCH * (CH + 1)];
__device__ int      g_idx[NN];
__device__ float    g_part[GROUPS * NN];

__device__ __forceinline__ unsigned key_of(float t) {
    unsigned b = __float_as_uint(t);
    return b ^ ((unsigned)((int)b >> 31) | 0x80000000u);
}

__global__ void __launch_bounds__(CH)
sort_kernel(const float* __restrict__ theta, const float* __restrict__ T,
            int n, float* __restrict__ out) {
    __shared__ ull   skv[CH];
    __shared__ float se [CH];
    __shared__ float swarp[CH / 32];
    __shared__ float soff [CH / 32];

    const int c    = blockIdx.x;
    const int t    = threadIdx.x;
    const int lane = t & 31;
    const int w    = t >> 5;
    const int j    = c * CH + t;

    ull kv = (j < n) ? (((ull)key_of(T[j]) << 32) | (unsigned)j) : (ull)t;

    // warp-bitonic sort ascending (15 shuffle substages, no barriers)
#pragma unroll
    for (int k = 2; k <= 32; k <<= 1) {
#pragma unroll
        for (int s = k >> 1; s > 0; s >>= 1) {
            const bool keep_min = (((lane & s) == 0) == ((lane & k) == 0));
            const ull pkv = __shfl_xor_sync(0xFFFFFFFFu, kv, s);
            const bool take = keep_min ? (pkv < kv) : (pkv > kv);
            if (take) kv = pkv;
        }
    }

    skv[w * 32 + lane] = kv;
    __syncthreads();

    // rank = lane + lower_bound in each other run; FULL range [0,32] per run
    int rank = lane;
#pragma unroll
    for (int r = 1; r < 8; r++) {
        const ull* __restrict__ A = skv + (((w + r) & 7) << 5);
        int lo = 0;
#pragma unroll
        for (int s = 16; s > 0; s >>= 1)
            if (A[lo + s - 1] < kv) lo += s;
        if (A[lo] < kv) lo++;                 // extend to count==32
        rank += lo;
    }

    const int   idx = (int)(unsigned)kv;
    const float e   = (idx < n) ? expf(theta[idx]) : 0.0f;
    g_u  [c * CH + rank] = (unsigned)(kv >> 32);
    g_idx[c * CH + rank] = idx;
    se[rank] = e;
    __syncthreads();

    // inclusive suffix sum of se
    float ssum = se[t];
#pragma unroll
    for (int off = 1; off < 32; off <<= 1) {
        float v = __shfl_down_sync(0xFFFFFFFFu, ssum, off);
        if (lane + off < 32) ssum += v;
    }
    if (lane == 0) swarp[w] = ssum;
    __syncthreads();
    if (t < CH / 32) {
        float v = swarp[t];
#pragma unroll
        for (int off = 1; off < CH / 32; off <<= 1) {
            float x = __shfl_down_sync(0xFFu, v, off);
            if (t + off < CH / 32) v += x;
        }
        soff[t] = v - swarp[t];
    }
    __syncthreads();

    g_sfx[c * (CH + 1) + t] = ssum + soff[w];
    if (t == 0) {
        g_sfx[c * (CH + 1) + CH] = 0.0f;
        if (c == 0) out[0] = 0.0f;
    }
}

__global__ void __launch_bounds__(RB)
rank_kernel() {
    __shared__ unsigned ck[CPG][CH];
    __shared__ float    cs[CPG][CH + 1];

    const int b    = blockIdx.x;
    const int tile = b / GROUPS;
    const int grp  = b % GROUPS;
    const int t    = threadIdx.x;

    const unsigned u = g_u[tile * RB + t];

    for (int i = t; i < CPG * CH; i += RB) {
        const int q = i >> 8, r = i & (CH - 1);
        ck[q][r] = g_u[(grp * CPG + q) * CH + r];
    }
    for (int i = t; i < CPG * (CH + 1); i += RB) {
        const int q = i / (CH + 1), r = i % (CH + 1);
        cs[q][r] = g_sfx[(grp * CPG + q) * (CH + 1) + r];
    }
    __syncthreads();

    int lo[CPG];
#pragma unroll
    for (int q = 0; q < CPG; q++) lo[q] = 0;
#pragma unroll
    for (int s = CH / 2; s > 0; s >>= 1) {
#pragma unroll
        for (int q = 0; q < CPG; q++)
            if (ck[q][lo[q] + s - 1] < u) lo[q] += s;
    }
#pragma unroll
    for (int q = 0; q < CPG; q++)             // extend to count==256 (cs has sentinel)
        if (ck[q][lo[q]] < u) lo[q]++;

    float acc = 0.0f;
#pragma unroll
    for (int q = 0; q < CPG; q++) acc += cs[q][lo[q]];

    g_part[grp * NN + tile * RB + t] = acc;
}

__global__ void __launch_bounds__(RB)
loss_kernel(const float* __restrict__ theta, const float* __restrict__ ev,
            int n, float* __restrict__ out) {
    const int s = blockIdx.x * RB + threadIdx.x;

    float term = 0.0f;
    if (s < n) {
        float rss = 0.0f;
#pragma unroll
        for (int g = 0; g < GROUPS; g++) rss += g_part[g * NN + s];
        const int io = g_idx[s];
        term = (theta[io] - logf(rss)) * ev[io];
    }

    for (int off = 16; off > 0; off >>= 1)
        term += __shfl_down_sync(0xFFFFFFFFu, term, off);

    __shared__ float wsum[RB / 32];
    const int lane = threadIdx.x & 31, warp = threadIdx.x >> 5;
    if (lane == 0) wsum[warp] = term;
    __syncthreads();
    if (threadIdx.x == 0) {
        float ssum = 0.0f;
#pragma unroll
        for (int w = 0; w < RB / 32; w++) ssum += wsum[w];
        atomicAdd(out, -ssum / (float)n);
    }
}

extern "C" void kernel_launch(void* const* d_in, const int* in_sizes, int n_in,
                              void* d_out, int out_size) {
    const float* theta = (const float*)d_in[0];
    const float* T     = (const float*)d_in[1];
    const float* ev    = (const float*)d_in[2];
    float*       out   = (float*)d_out;
    const int n = in_sizes[0];

    sort_kernel<<<NCH, CH>>>(theta, T, n, out);
    rank_kernel<<<TILES * GROUPS, RB>>>();
    loss_kernel<<<TILES, RB>>>(theta, ev, n, out);
}